// round 7
// baseline (speedup 1.0000x reference)
#include <cuda_runtime.h>
#include <cuda_fp16.h>

// out[v,:] = coef * ( 2*x[v,:]*S1 + S2 ), S1 = sum_k x[nbr[v,k]], S2 = sum_k x[nbr[v,k]]^2
// N=100000, K=16, D=128, coef = (2/6)/16 = 1/48.
// fp16 gather route. Main kernel is issue-slot bound, so:
//  - 2 nodes per warp: lanes 0-15 = node 2w, lanes 16-31 = node 2w+1.
//    Each lane owns a uint4 (8 halves) of the 256B fp16 row, so ONE LDG.128
//    serves the k-th gather of BOTH nodes (8 gather instrs per node, was 16).
//  - idx via int4 loads (2 instrs per node, was 16).
//  - half2 accumulation in runs of 8, flushed to fp32 (2 flushes, was 4).

#define TMP_N 100000
#define TMP_D 128
#define TMP_K 16

// fp16 copy of x: row v = 16 uint4 (128 halves).
__device__ __align__(16) uint4 g_xh4[TMP_N * TMP_D / 8];

__global__ __launch_bounds__(256) void TMP_convert_kernel(
    const float4* __restrict__ x, int n8)
{
    int i = blockIdx.x * blockDim.x + threadIdx.x;
    if (i >= n8) return;
    float4 a = __ldg(&x[2 * i]);
    float4 b = __ldg(&x[2 * i + 1]);
    __half2 h0 = __floats2half2_rn(a.x, a.y);
    __half2 h1 = __floats2half2_rn(a.z, a.w);
    __half2 h2 = __floats2half2_rn(b.x, b.y);
    __half2 h3 = __floats2half2_rn(b.z, b.w);
    uint4 p;
    p.x = *reinterpret_cast<unsigned int*>(&h0);
    p.y = *reinterpret_cast<unsigned int*>(&h1);
    p.z = *reinterpret_cast<unsigned int*>(&h2);
    p.w = *reinterpret_cast<unsigned int*>(&h3);
    g_xh4[i] = p;
}

static __device__ __forceinline__ __half2 h2bits(unsigned int u) {
    return *reinterpret_cast<__half2*>(&u);
}

__global__ __launch_bounds__(256) void TMessagePassing_11974368821731_kernel(
    const int4* __restrict__ nbr4,   // [N, 4] int4 (= [N,16] int)
    float4*     __restrict__ out,    // [N, 32] float4
    int n)
{
    int warp = (int)((blockIdx.x * blockDim.x + threadIdx.x) >> 5);
    int lane = threadIdx.x & 31;
    int half = lane >> 4;            // 0: node 2w, 1: node 2w+1
    int l16  = lane & 15;
    int node = 2 * warp + half;
    if (2 * warp >= n) return;
    bool active = node < n;
    int srcnode = active ? node : (n - 1);

    const float coef = 1.0f / 48.0f;

    // 16 neighbor indices of THIS half's node (4x int4, broadcast per half-warp).
    const int4* nv = nbr4 + (long long)srcnode * 4;
    int idx[TMP_K];
#pragma unroll
    for (int r = 0; r < 4; r++) {
        int4 q = __ldg(&nv[r]);
        idx[4 * r + 0] = q.x; idx[4 * r + 1] = q.y;
        idx[4 * r + 2] = q.z; idx[4 * r + 3] = q.w;
    }

    const uint4* __restrict__ xh = g_xh4;

    // Self row (fp16, L2-resident), issued early.
    uint4 ps = __ldg(xh + ((unsigned)srcnode * 16u + (unsigned)l16));

    float s1f[8], s2f[8];
#pragma unroll
    for (int j = 0; j < 8; j++) { s1f[j] = 0.f; s2f[j] = 0.f; }

    // 2 runs of 8 gathers; half2 accumulation within a run, fp32 flush after.
#pragma unroll
    for (int run = 0; run < 2; run++) {
        __half2 s1h[4], s2h[4];
        {
            uint4 p = __ldg(xh + ((unsigned)idx[8 * run] * 16u + (unsigned)l16));
            __half2 a0 = h2bits(p.x), a1 = h2bits(p.y), a2 = h2bits(p.z), a3 = h2bits(p.w);
            s1h[0] = a0; s1h[1] = a1; s1h[2] = a2; s1h[3] = a3;
            s2h[0] = __hmul2(a0, a0); s2h[1] = __hmul2(a1, a1);
            s2h[2] = __hmul2(a2, a2); s2h[3] = __hmul2(a3, a3);
        }
#pragma unroll
        for (int j = 1; j < 8; j++) {
            uint4 p = __ldg(xh + ((unsigned)idx[8 * run + j] * 16u + (unsigned)l16));
            __half2 a0 = h2bits(p.x), a1 = h2bits(p.y), a2 = h2bits(p.z), a3 = h2bits(p.w);
            s1h[0] = __hadd2(s1h[0], a0); s1h[1] = __hadd2(s1h[1], a1);
            s1h[2] = __hadd2(s1h[2], a2); s1h[3] = __hadd2(s1h[3], a3);
            s2h[0] = __hfma2(a0, a0, s2h[0]); s2h[1] = __hfma2(a1, a1, s2h[1]);
            s2h[2] = __hfma2(a2, a2, s2h[2]); s2h[3] = __hfma2(a3, a3, s2h[3]);
        }
#pragma unroll
        for (int j = 0; j < 4; j++) {
            float2 f1 = __half22float2(s1h[j]);
            float2 f2 = __half22float2(s2h[j]);
            s1f[2 * j]     += f1.x; s1f[2 * j + 1] += f1.y;
            s2f[2 * j]     += f2.x; s2f[2 * j + 1] += f2.y;
        }
    }

    // o[j] = coef * ( 2*xv[j]*S1[j] + S2[j] )
    float xv[8];
    {
        float2 f;
        f = __half22float2(h2bits(ps.x)); xv[0] = f.x; xv[1] = f.y;
        f = __half22float2(h2bits(ps.y)); xv[2] = f.x; xv[3] = f.y;
        f = __half22float2(h2bits(ps.z)); xv[4] = f.x; xv[5] = f.y;
        f = __half22float2(h2bits(ps.w)); xv[6] = f.x; xv[7] = f.y;
    }
    float o[8];
#pragma unroll
    for (int j = 0; j < 8; j++)
        o[j] = coef * fmaf(xv[j] + xv[j], s1f[j], s2f[j]);

    if (active) {
        float4* ob = out + ((long long)node * 32 + 2 * l16);
        float4 o0 = make_float4(o[0], o[1], o[2], o[3]);
        float4 o1 = make_float4(o[4], o[5], o[6], o[7]);
        __stcs(ob, o0);
        __stcs(ob + 1, o1);
    }
}

extern "C" void kernel_launch(void* const* d_in, const int* in_sizes, int n_in,
                              void* d_out, int out_size)
{
    const float4* x    = (const float4*)d_in[0];
    const int4*   nbr4 = (const int4*)d_in[1];
    float4*       out  = (float4*)d_out;

    int n  = in_sizes[1] / TMP_K;      // N nodes
    int n8 = in_sizes[0] / 8;          // N*D/8 uint4s

    TMP_convert_kernel<<<(n8 + 255) / 256, 256>>>(x, n8);

    // 8 warps/block, 2 nodes/warp -> 16 nodes per block.
    int blocks = (n + 15) / 16;
    TMessagePassing_11974368821731_kernel<<<blocks, 256>>>(nbr4, out, n);
}

// round 8
// speedup vs baseline: 1.3382x; 1.3382x over previous
#include <cuda_runtime.h>
#include <cuda_fp16.h>

// out[v,:] = coef * ( 2*x[v,:]*S1 + S2 ), S1 = sum_k x[nbr[v,k]], S2 = sum_k x[nbr[v,k]]^2
// N=100000, K=16, D=128, coef = (2/6)/16 = 1/48.
// fp16 gather route, 1 node/warp (R7 showed 2/warp regresses).
//  - idx via 4x int4 (saves 12 L1 wavefronts + 12 issue slots/warp)
//  - 16 independent LDG.64 gathers of 256B fp16 rows
//  - half2 accumulation in runs of 8, fp32 flush (2 flushes)
//  - self row from fp16 scratch; out stored streaming (evict-first)
//  - convert reads x with __ldcs so x never pollutes L2; xh stays resident.

#define TMP_N 100000
#define TMP_D 128
#define TMP_K 16

// fp16 copy of x: [N, 32] uint2 (4 halves per lane).
__device__ __align__(16) uint2 g_xh[TMP_N * TMP_D / 4];

__global__ __launch_bounds__(256) void TMP_convert_kernel(
    const float4* __restrict__ x, int n4)
{
    int i = blockIdx.x * blockDim.x + threadIdx.x;
    if (i >= n4) return;
    float4 v = __ldcs(&x[i]);   // evict-first: x is single-use per launch
    __half2 h0 = __floats2half2_rn(v.x, v.y);
    __half2 h1 = __floats2half2_rn(v.z, v.w);
    uint2 p;
    p.x = *reinterpret_cast<unsigned int*>(&h0);
    p.y = *reinterpret_cast<unsigned int*>(&h1);
    g_xh[i] = p;
}

static __device__ __forceinline__ __half2 h2bits(unsigned int u) {
    return *reinterpret_cast<__half2*>(&u);
}

__global__ __launch_bounds__(256) void TMessagePassing_11974368821731_kernel(
    const int4* __restrict__ nbr4,   // [N, 4] int4 (= [N,16] int)
    float4*     __restrict__ out,    // [N, 32] float4
    int n)
{
    int warp = (int)((blockIdx.x * blockDim.x + threadIdx.x) >> 5);
    int lane = threadIdx.x & 31;
    if (warp >= n) return;

    const float coef = 1.0f / 48.0f;
    const uint2* __restrict__ xh = g_xh;

    // 16 neighbor indices via 4 vector loads (uniform -> broadcast).
    const int4* nv = nbr4 + (long long)warp * 4;
    int idx[TMP_K];
#pragma unroll
    for (int r = 0; r < 4; r++) {
        int4 q = __ldg(&nv[r]);
        idx[4 * r + 0] = q.x; idx[4 * r + 1] = q.y;
        idx[4 * r + 2] = q.z; idx[4 * r + 3] = q.w;
    }

    // Self row (fp16, L2-resident), issued early.
    uint2 ps = __ldg(&xh[(unsigned)warp * 32u + (unsigned)lane]);

    float4 s1 = make_float4(0.f, 0.f, 0.f, 0.f);
    float4 s2 = make_float4(0.f, 0.f, 0.f, 0.f);

    // 2 runs of 8 gathers; half2 accumulation within a run, fp32 flush after.
#pragma unroll
    for (int run = 0; run < 2; run++) {
        __half2 t0, t1, q0, q1;
        {
            uint2 p = __ldg(&xh[(unsigned)idx[8 * run] * 32u + (unsigned)lane]);
            __half2 a0 = h2bits(p.x), a1 = h2bits(p.y);
            t0 = a0;              t1 = a1;
            q0 = __hmul2(a0, a0); q1 = __hmul2(a1, a1);
        }
#pragma unroll
        for (int j = 1; j < 8; j++) {
            uint2 p = __ldg(&xh[(unsigned)idx[8 * run + j] * 32u + (unsigned)lane]);
            __half2 a0 = h2bits(p.x), a1 = h2bits(p.y);
            t0 = __hadd2(t0, a0);     t1 = __hadd2(t1, a1);
            q0 = __hfma2(a0, a0, q0); q1 = __hfma2(a1, a1, q1);
        }
        float2 f;
        f = __half22float2(t0); s1.x += f.x; s1.y += f.y;
        f = __half22float2(t1); s1.z += f.x; s1.w += f.y;
        f = __half22float2(q0); s2.x += f.x; s2.y += f.y;
        f = __half22float2(q1); s2.z += f.x; s2.w += f.y;
    }

    float2 xv0 = __half22float2(h2bits(ps.x));
    float2 xv1 = __half22float2(h2bits(ps.y));

    float4 o;
    o.x = coef * fmaf(xv0.x + xv0.x, s1.x, s2.x);
    o.y = coef * fmaf(xv0.y + xv0.y, s1.y, s2.y);
    o.z = coef * fmaf(xv1.x + xv1.x, s1.z, s2.z);
    o.w = coef * fmaf(xv1.y + xv1.y, s1.w, s2.w);

    // Streaming store: keep out from evicting xh in L2.
    __stcs(&out[(long long)warp * 32 + lane], o);
}

extern "C" void kernel_launch(void* const* d_in, const int* in_sizes, int n_in,
                              void* d_out, int out_size)
{
    const float4* x    = (const float4*)d_in[0];
    const int4*   nbr4 = (const int4*)d_in[1];
    float4*       out  = (float4*)d_out;

    int n  = in_sizes[1] / TMP_K;      // N nodes
    int n4 = in_sizes[0] / 4;          // N*D/4 float4s

    TMP_convert_kernel<<<(n4 + 255) / 256, 256>>>(x, n4);

    int warps_per_block = 256 / 32;    // 8 nodes per block
    int blocks = (n + warps_per_block - 1) / warps_per_block;
    TMessagePassing_11974368821731_kernel<<<blocks, 256>>>(nbr4, out, n);
}